// round 15
// baseline (speedup 1.0000x reference)
#include <cuda_runtime.h>
#include <cuda_fp16.h>

// ---------------------------------------------------------------------------
// CharEmbeddingCNN: embed + 3x conv1d(k=3,4,5) + maxpool + relu + len-mask.
//
//   C_kj[c, o] = sum_i W_k[o, i, j] * emb[c, i]      (12 tables, 256x256, fp16)
//   y_k[n,o,t] = b_k[o] + sum_j C_kj[x[n,t+j], o]
//   out[n,o]   = mask(n) * relu(max_{k,t} y_k[n,o,t])
//
// R15: R14 (best 49.1us) with the inner t-loop restructured: all K window
// loads issued up-front (explicit MLP), then TREE-reduced (K=4 depth 2,
// K=5 depth 3) so one slow LDS no longer stalls the whole window chain.
// ---------------------------------------------------------------------------

#define LSEQ  20
#define NTOT  8192            // 64 * 128
#define NPC   222             // n per CTA (37 groups)
#define NGRP  37
#define OTILES 4              // 4 tiles of 64 outputs
#define TBL_BYTES 32768       // per-slot SMEM slice: 256 chars * 64 halves * 2B
#define NSLOTS 5
#define CHSTRIDE 24           // shorts per n (20 used, padded for uint4)
#define SMEM_CHARS_OFF (NSLOTS * TBL_BYTES)
#define SMEM_TOTAL (SMEM_CHARS_OFF + NPC * CHSTRIDE * 2)
#define NCTA  148
#define BSTRIDE 72            // halves per staged build row (64 data + 8 pad)

__device__ __align__(16) __half g_tbl_h[12 * 256 * 256];
__device__ unsigned g_count = 0;
__device__ volatile unsigned g_gen = 0;

// ---------------------------------------------------------------------------
// cp.async helpers
// ---------------------------------------------------------------------------
#define CP_ASYNC16(dst, src) \
    asm volatile("cp.async.cg.shared.global [%0], [%1], 16;" :: "r"(dst), "l"(src))
#define CP_COMMIT() asm volatile("cp.async.commit_group;")
#define CP_WAIT0()  asm volatile("cp.async.wait_group 0;" ::: "memory")

// Stage one 32KB table slice (256 rows x 128B) into SMEM slot.
__device__ __forceinline__ void stage_slice(
    unsigned sm_u32, int slot, const __half* __restrict__ src, int tid)
{
    const unsigned dst0 = sm_u32 + slot * TBL_BYTES;
    #pragma unroll
    for (int r = 0; r < 2; r++) {
        int idx = tid + r * 1024;          // 0..2047 16B chunks
        CP_ASYNC16(dst0 + idx * 16, src + (idx >> 3) * 256 + (idx & 7) * 8);
    }
}

// ---------------------------------------------------------------------------
// Tensor-core table build, 1024 threads per job (R13 version, unchanged).
// One job = 128c x 64o x 256k; tbl=job>>3, c0=((job>>2)&1)*128, o0=(job&3)*64.
// Warp w: row-block = w&7 (m16 rows), on-pair = w>>3 (2 of 8 n8-tiles).
// k-chunk 64 (4 chunks). Split-fp16: 3 mma passes hi*hi + hi*lo + lo*hi.
// ---------------------------------------------------------------------------
__device__ __forceinline__ void mma_16816(
    float d[4], unsigned a0, unsigned a1, unsigned a2, unsigned a3,
    unsigned b0, unsigned b1)
{
    asm volatile(
        "mma.sync.aligned.m16n8k16.row.col.f32.f16.f16.f32 "
        "{%0,%1,%2,%3}, {%4,%5,%6,%7}, {%8,%9}, {%0,%1,%2,%3};"
        : "+f"(d[0]), "+f"(d[1]), "+f"(d[2]), "+f"(d[3])
        : "r"(a0), "r"(a1), "r"(a2), "r"(a3), "r"(b0), "r"(b1));
}

__device__ __forceinline__ unsigned pack_hi(float x, float y) {
    __half2 h = __halves2half2(__float2half_rn(x), __float2half_rn(y));
    return *reinterpret_cast<unsigned*>(&h);
}
__device__ __forceinline__ unsigned pack_lo(float x, float y) {
    __half hx = __float2half_rn(x), hy = __float2half_rn(y);
    __half2 h = __halves2half2(__float2half_rn(x - __half2float(hx)),
                               __float2half_rn(y - __half2float(hy)));
    return *reinterpret_cast<unsigned*>(&h);
}

__device__ void build_job_tc(
    int job, char* smraw,
    const float* __restrict__ emb,
    const float* __restrict__ w3, const float* __restrict__ w4,
    const float* __restrict__ w5, int tid)
{
    const int tbl = job >> 3;
    const int c0  = ((job >> 2) & 1) * 128;
    const int o0  = (job & 3) * 64;

    int k, j; const float* w;
    if (tbl < 3)      { k = 3; j = tbl;     w = w3; }
    else if (tbl < 7) { k = 4; j = tbl - 3; w = w4; }
    else              { k = 5; j = tbl - 7; w = w5; }
    const int wk = 256 * k;

    __half* Ahi = reinterpret_cast<__half*>(smraw);
    __half* Alo = Ahi + 128 * BSTRIDE;
    __half* Bhi = Alo + 128 * BSTRIDE;
    __half* Blo = Bhi + 64 * BSTRIDE;

    const int warp    = tid >> 5;
    const int lane    = tid & 31;
    const int grp     = lane >> 2;
    const int tig     = lane & 3;
    const int rowblk  = warp & 7;
    const int on_pair = warp >> 3;       // 0..3 -> n8-tiles {2p, 2p+1}
    const int r0      = rowblk * 16 + grp;

    float d[2][4];
    #pragma unroll
    for (int oi = 0; oi < 2; oi++)
        #pragma unroll
        for (int u = 0; u < 4; u++) d[oi][u] = 0.0f;

    for (int chunk = 0; chunk < 4; chunk++) {
        const int i0 = chunk * 64;
        __syncthreads();                        // mma done with smem
        #pragma unroll
        for (int r = 0; r < 4; r++) {           // A: 128c x 64i (32 pairs/row)
            int idx = tid + r * 1024;
            int c   = idx >> 5;
            int p   = idx & 31;
            float2 e = *reinterpret_cast<const float2*>(
                emb + (c0 + c) * 256 + i0 + 2 * p);
            *reinterpret_cast<unsigned*>(&Ahi[c * BSTRIDE + 2 * p]) = pack_hi(e.x, e.y);
            *reinterpret_cast<unsigned*>(&Alo[c * BSTRIDE + 2 * p]) = pack_lo(e.x, e.y);
        }
        #pragma unroll
        for (int r = 0; r < 2; r++) {           // B: 64o x 64i
            int idx = tid + r * 1024;
            int o   = idx >> 5;
            int p   = idx & 31;
            const float* wp = w + (o0 + o) * wk + (i0 + 2 * p) * k + j;
            float vx = wp[0], vy = wp[k];
            *reinterpret_cast<unsigned*>(&Bhi[o * BSTRIDE + 2 * p]) = pack_hi(vx, vy);
            *reinterpret_cast<unsigned*>(&Blo[o * BSTRIDE + 2 * p]) = pack_lo(vx, vy);
        }
        __syncthreads();                        // smem ready

        #pragma unroll
        for (int kc = 0; kc < 64; kc += 16) {
            unsigned ah0 = *reinterpret_cast<unsigned*>(&Ahi[ r0      * BSTRIDE + kc     + 2 * tig]);
            unsigned ah1 = *reinterpret_cast<unsigned*>(&Ahi[(r0 + 8) * BSTRIDE + kc     + 2 * tig]);
            unsigned ah2 = *reinterpret_cast<unsigned*>(&Ahi[ r0      * BSTRIDE + kc + 8 + 2 * tig]);
            unsigned ah3 = *reinterpret_cast<unsigned*>(&Ahi[(r0 + 8) * BSTRIDE + kc + 8 + 2 * tig]);
            unsigned al0 = *reinterpret_cast<unsigned*>(&Alo[ r0      * BSTRIDE + kc     + 2 * tig]);
            unsigned al1 = *reinterpret_cast<unsigned*>(&Alo[(r0 + 8) * BSTRIDE + kc     + 2 * tig]);
            unsigned al2 = *reinterpret_cast<unsigned*>(&Alo[ r0      * BSTRIDE + kc + 8 + 2 * tig]);
            unsigned al3 = *reinterpret_cast<unsigned*>(&Alo[(r0 + 8) * BSTRIDE + kc + 8 + 2 * tig]);
            #pragma unroll
            for (int oi = 0; oi < 2; oi++) {
                int on = on_pair * 2 + oi;
                int ob = (on * 8 + grp) * BSTRIDE;
                unsigned bh0 = *reinterpret_cast<unsigned*>(&Bhi[ob + kc     + 2 * tig]);
                unsigned bh1 = *reinterpret_cast<unsigned*>(&Bhi[ob + kc + 8 + 2 * tig]);
                unsigned bl0 = *reinterpret_cast<unsigned*>(&Blo[ob + kc     + 2 * tig]);
                unsigned bl1 = *reinterpret_cast<unsigned*>(&Blo[ob + kc + 8 + 2 * tig]);
                mma_16816(d[oi], ah0, ah1, ah2, ah3, bh0, bh1);
                mma_16816(d[oi], ah0, ah1, ah2, ah3, bl0, bl1);
                mma_16816(d[oi], al0, al1, al2, al3, bh0, bh1);
            }
        }
    }

    #pragma unroll
    for (int oi = 0; oi < 2; oi++) {
        int on  = on_pair * 2 + oi;
        int col = o0 + on * 8 + 2 * tig;
        __half2 h01 = __floats2half2_rn(d[oi][0], d[oi][1]);
        __half2 h23 = __floats2half2_rn(d[oi][2], d[oi][3]);
        *reinterpret_cast<unsigned*>(
            &g_tbl_h[tbl * 65536 + (c0 + r0) * 256 + col]) =
            *reinterpret_cast<unsigned*>(&h01);
        *reinterpret_cast<unsigned*>(
            &g_tbl_h[tbl * 65536 + (c0 + r0 + 8) * 256 + col]) =
            *reinterpret_cast<unsigned*>(&h23);
    }
}

// ---------------------------------------------------------------------------
// Pool compute phase: loads first (explicit MLP), then tree-reduced adds.
// ---------------------------------------------------------------------------
#define H2(u) (*reinterpret_cast<__half2*>(&(u)))
#define TREE3(c) __hadd2(__hadd2(H2(ld[0].c), H2(ld[1].c)), H2(ld[2].c))
#define TREE4(c) __hadd2(__hadd2(H2(ld[0].c), H2(ld[1].c)), \
                         __hadd2(H2(ld[2].c), H2(ld[3].c)))
#define TREE5(c) __hadd2(TREE4(c), H2(ld[4].c))

template<int K, int S0, int S1, int S2, int S3, int S4>
__device__ __forceinline__ void compute_phase(
    char* sm, const unsigned short* schars,
    const float* __restrict__ bias,
    __half2 acc[2][4],
    int otile, int n_count, int qtotal,
    int warp, int n_sub, unsigned lane_off)
{
    constexpr unsigned SB[5] = {S0 * TBL_BYTES, S1 * TBL_BYTES, S2 * TBL_BYTES,
                                S3 * TBL_BYTES, S4 * TBL_BYTES};

    const float* bp = bias + otile * 64 + (lane_off >> 1);
    __half2 bh[4];
    #pragma unroll
    for (int c = 0; c < 4; c++)
        bh[c] = __floats2half2_rn(bp[2 * c], bp[2 * c + 1]);

    const __half2 NEGINF = __float2half2_rn(-60000.0f);

    #pragma unroll
    for (int it = 0; it < 2; it++) {
        const int q = warp + it * 32;
        if (q < qtotal) {
            const int nl  = q * 4 + n_sub;
            const int nlc = (nl < n_count) ? nl : (n_count - 1);

            const unsigned short* cp = schars + nlc * CHSTRIDE;
            uint4 p0 = *reinterpret_cast<const uint4*>(cp);
            uint4 p1 = *reinterpret_cast<const uint4*>(cp + 8);
            uint2 p2 = *reinterpret_cast<const uint2*>(cp + 16);
            unsigned pk[10] = {p0.x, p0.y, p0.z, p0.w,
                               p1.x, p1.y, p1.z, p1.w, p2.x, p2.y};
            unsigned a[LSEQ];
            #pragma unroll
            for (int p = 0; p < LSEQ; p++)
                a[p] = ((pk[p >> 1] >> (16 * (p & 1))) & 0xFFFFu) + lane_off;

            __half2 m0 = NEGINF, m1 = NEGINF, m2 = NEGINF, m3 = NEGINF;
            #pragma unroll
            for (int t = 0; t <= LSEQ - K; t++) {
                // all K window loads issued up-front (max MLP per window)
                uint4 ld[K];
                #pragma unroll
                for (int j = 0; j < K; j++)
                    ld[j] = *reinterpret_cast<const uint4*>(
                        sm + SB[j] + a[t + j]);

                __half2 s0, s1, s2, s3;
                if constexpr (K == 3) {
                    s0 = TREE3(x); s1 = TREE3(y); s2 = TREE3(z); s3 = TREE3(w);
                } else if constexpr (K == 4) {
                    s0 = TREE4(x); s1 = TREE4(y); s2 = TREE4(z); s3 = TREE4(w);
                } else {
                    s0 = TREE5(x); s1 = TREE5(y); s2 = TREE5(z); s3 = TREE5(w);
                }

                m0 = __hmax2(m0, s0);
                m1 = __hmax2(m1, s1);
                m2 = __hmax2(m2, s2);
                m3 = __hmax2(m3, s3);
            }

            acc[it][0] = __hmax2(acc[it][0], __hadd2(m0, bh[0]));
            acc[it][1] = __hmax2(acc[it][1], __hadd2(m1, bh[1]));
            acc[it][2] = __hmax2(acc[it][2], __hadd2(m2, bh[2]));
            acc[it][3] = __hmax2(acc[it][3], __hadd2(m3, bh[3]));
        }
    }
}

// ---------------------------------------------------------------------------
__global__ void __launch_bounds__(1024, 1)
fused_cnn_kernel(const int* __restrict__ x, const int* __restrict__ lens,
                 const float* __restrict__ emb,
                 const float* __restrict__ w3, const float* __restrict__ b3,
                 const float* __restrict__ w4, const float* __restrict__ b4,
                 const float* __restrict__ w5, const float* __restrict__ b5,
                 float* __restrict__ out)
{
    extern __shared__ char sm[];
    const int tid     = threadIdx.x;
    const int group   = blockIdx.x;
    const int otile   = blockIdx.y;
    const int bid     = otile * NGRP + group;     // 0..147
    const int n_start = group * NPC;
    const int n_count = min(NTOT - n_start, NPC);

    unsigned short* schars = reinterpret_cast<unsigned short*>(sm + SMEM_CHARS_OFF);
    const bool builder = (bid < 96);              // CTA-uniform

    // ---- prologue: builder CTAs run the build with ALL 1024 threads
    //      (chars staged later, overlapped with boundary-1 cp.async wait);
    //      non-builder CTAs stage chars with all 1024 threads.
    if (builder) {
        build_job_tc(bid, sm, emb, w3, w4, w5, tid);
    } else {
        for (int i = tid; i < n_count * LSEQ; i += 1024) {
            int n = i / LSEQ, p = i - n * LSEQ;
            schars[n * CHSTRIDE + p] =
                (unsigned short)(x[(n_start + n) * LSEQ + p] << 7);
        }
    }

    // ---- grid barrier (sense-reversing via generation counter; replay-safe)
    __threadfence();
    __syncthreads();
    if (tid == 0) {
        unsigned gen = g_gen;
        __threadfence();
        if (atomicAdd(&g_count, 1) == NCTA - 1) {
            atomicExch(&g_count, 0);
            __threadfence();
            g_gen = gen + 1;
        } else {
            while (g_gen == gen) { }
        }
    }
    __syncthreads();

    // ---- pool: 5-slot, ALL staging exposed at boundaries (R14 proven).
    //      phase3 {0,1,2}; phase4 {3,4,0,1}; phase5 {2,3,4,0,1}.
    const unsigned sm_u32 = (unsigned)__cvta_generic_to_shared(sm);
    const __half* T = g_tbl_h + otile * 64;

    const int lane  = tid & 31;
    const int warp  = tid >> 5;
    const int n_sub = lane >> 3;
    const unsigned lane_off = (unsigned)((lane & 7) * 16);
    const int qtotal = (n_count + 3) >> 2;

    __half2 acc[2][4];
    #pragma unroll
    for (int i = 0; i < 2; i++)
        #pragma unroll
        for (int c = 0; c < 4; c++) acc[i][c] = __float2half2_rn(0.0f);

    // boundary 1: stage k3 (slots 0-2); builder CTAs stage chars under the
    // cp.async wait (LDG latency overlaps the 96KB slot transfer).
    stage_slice(sm_u32, 0, T + 0 * 65536, tid);
    stage_slice(sm_u32, 1, T + 1 * 65536, tid);
    stage_slice(sm_u32, 2, T + 2 * 65536, tid);
    CP_COMMIT();
    if (builder) {
        for (int i = tid; i < n_count * LSEQ; i += 1024) {
            int n = i / LSEQ, p = i - n * LSEQ;
            schars[n * CHSTRIDE + p] =
                (unsigned short)(x[(n_start + n) * LSEQ + p] << 7);
        }
    }
    CP_WAIT0(); __syncthreads();

    compute_phase<3, 0, 1, 2, 0, 0>(sm, schars, b3, acc, otile, n_count,
                                    qtotal, warp, n_sub, lane_off);

    // boundary 2: stage k4 j0-3 -> slots 3,4,0,1 (k3 done)
    __syncthreads();
    stage_slice(sm_u32, 3, T + 3 * 65536, tid);
    stage_slice(sm_u32, 4, T + 4 * 65536, tid);
    stage_slice(sm_u32, 0, T + 5 * 65536, tid);
    stage_slice(sm_u32, 1, T + 6 * 65536, tid);
    CP_COMMIT(); CP_WAIT0(); __syncthreads();

    compute_phase<4, 3, 4, 0, 1, 0>(sm, schars, b4, acc, otile, n_count,
                                    qtotal, warp, n_sub, lane_off);

    // boundary 3: stage k5 j0-4 -> slots 2,3,4,0,1 (k4 done)
    __syncthreads();
    stage_slice(sm_u32, 2, T +  7 * 65536, tid);
    stage_slice(sm_u32, 3, T +  8 * 65536, tid);
    stage_slice(sm_u32, 4, T +  9 * 65536, tid);
    stage_slice(sm_u32, 0, T + 10 * 65536, tid);
    stage_slice(sm_u32, 1, T + 11 * 65536, tid);
    CP_COMMIT(); CP_WAIT0(); __syncthreads();

    compute_phase<5, 2, 3, 4, 0, 1>(sm, schars, b5, acc, otile, n_count,
                                    qtotal, warp, n_sub, lane_off);

    // ---- epilogue: one pure store per (n, 8-output slice); masked -> zeros.
    #pragma unroll
    for (int it = 0; it < 2; it++) {
        const int q  = warp + it * 32;
        const int nl = q * 4 + n_sub;
        if (q < qtotal && nl < n_count) {
            const int n = n_start + nl;
            float4 o0 = make_float4(0.f, 0.f, 0.f, 0.f);
            float4 o1 = o0;
            if (lens[n] != 0) {
                float2 f0 = __half22float2(acc[it][0]);
                float2 f1 = __half22float2(acc[it][1]);
                float2 f2 = __half22float2(acc[it][2]);
                float2 f3 = __half22float2(acc[it][3]);
                o0 = make_float4(f0.x, f0.y, f1.x, f1.y);
                o1 = make_float4(f2.x, f2.y, f3.x, f3.y);
            }
            float4* po = reinterpret_cast<float4*>(
                &out[(size_t)n * 256 + otile * 64 + (lane_off >> 1)]);
            po[0] = o0;
            po[1] = o1;
        }
    }
}

// ---------------------------------------------------------------------------
extern "C" void kernel_launch(void* const* d_in, const int* in_sizes, int n_in,
                              void* d_out, int out_size)
{
    const int*   x    = (const int*)  d_in[0];
    const int*   lens = (const int*)  d_in[1];
    const float* emb  = (const float*)d_in[2];
    const float* w3   = (const float*)d_in[3];
    const float* b3   = (const float*)d_in[4];
    const float* w4   = (const float*)d_in[5];
    const float* b4   = (const float*)d_in[6];
    const float* w5   = (const float*)d_in[7];
    const float* b5   = (const float*)d_in[8];
    float* out = (float*)d_out;

    cudaFuncSetAttribute(fused_cnn_kernel,
                         cudaFuncAttributeMaxDynamicSharedMemorySize, SMEM_TOTAL);
    fused_cnn_kernel<<<dim3(NGRP, OTILES), 1024, SMEM_TOTAL>>>(
        x, lens, emb, w3, b3, w4, b4, w5, b5, out);
}

// round 16
// speedup vs baseline: 1.0138x; 1.0138x over previous
#include <cuda_runtime.h>
#include <cuda_fp16.h>

// ---------------------------------------------------------------------------
// CharEmbeddingCNN: embed + 3x conv1d(k=3,4,5) + maxpool + relu + len-mask.
//
//   C_kj[c, o] = sum_i W_k[o, i, j] * emb[c, i]      (12 tables, 256x256, fp16)
//   y_k[n,o,t] = b_k[o] + sum_j C_kj[x[n,t+j], o]
//   out[n,o]   = mask(n) * relu(max_{k,t} y_k[n,o,t])
//
// R16: R14 (best 49.1us) with the a[20] address array removed — addresses
// extracted inline from the packed pk words at each use (constant shifts
// under full unroll), freeing ~20 registers for LDS scheduling. Adds stay
// serial-chain (R14 order) -> bit-identical accumulation.
// ---------------------------------------------------------------------------

#define LSEQ  20
#define NTOT  8192            // 64 * 128
#define NPC   222             // n per CTA (37 groups)
#define NGRP  37
#define OTILES 4              // 4 tiles of 64 outputs
#define TBL_BYTES 32768       // per-slot SMEM slice: 256 chars * 64 halves * 2B
#define NSLOTS 5
#define CHSTRIDE 24           // shorts per n (20 used, padded for uint4)
#define SMEM_CHARS_OFF (NSLOTS * TBL_BYTES)
#define SMEM_TOTAL (SMEM_CHARS_OFF + NPC * CHSTRIDE * 2)
#define NCTA  148
#define BSTRIDE 72            // halves per staged build row (64 data + 8 pad)

__device__ __align__(16) __half g_tbl_h[12 * 256 * 256];
__device__ unsigned g_count = 0;
__device__ volatile unsigned g_gen = 0;

// ---------------------------------------------------------------------------
// cp.async helpers
// ---------------------------------------------------------------------------
#define CP_ASYNC16(dst, src) \
    asm volatile("cp.async.cg.shared.global [%0], [%1], 16;" :: "r"(dst), "l"(src))
#define CP_COMMIT() asm volatile("cp.async.commit_group;")
#define CP_WAIT0()  asm volatile("cp.async.wait_group 0;" ::: "memory")

// Stage one 32KB table slice (256 rows x 128B) into SMEM slot.
__device__ __forceinline__ void stage_slice(
    unsigned sm_u32, int slot, const __half* __restrict__ src, int tid)
{
    const unsigned dst0 = sm_u32 + slot * TBL_BYTES;
    #pragma unroll
    for (int r = 0; r < 2; r++) {
        int idx = tid + r * 1024;          // 0..2047 16B chunks
        CP_ASYNC16(dst0 + idx * 16, src + (idx >> 3) * 256 + (idx & 7) * 8);
    }
}

// ---------------------------------------------------------------------------
// Tensor-core table build, 1024 threads per job (R13 version, unchanged).
// One job = 128c x 64o x 256k; tbl=job>>3, c0=((job>>2)&1)*128, o0=(job&3)*64.
// Warp w: row-block = w&7 (m16 rows), on-pair = w>>3 (2 of 8 n8-tiles).
// k-chunk 64 (4 chunks). Split-fp16: 3 mma passes hi*hi + hi*lo + lo*hi.
// ---------------------------------------------------------------------------
__device__ __forceinline__ void mma_16816(
    float d[4], unsigned a0, unsigned a1, unsigned a2, unsigned a3,
    unsigned b0, unsigned b1)
{
    asm volatile(
        "mma.sync.aligned.m16n8k16.row.col.f32.f16.f16.f32 "
        "{%0,%1,%2,%3}, {%4,%5,%6,%7}, {%8,%9}, {%0,%1,%2,%3};"
        : "+f"(d[0]), "+f"(d[1]), "+f"(d[2]), "+f"(d[3])
        : "r"(a0), "r"(a1), "r"(a2), "r"(a3), "r"(b0), "r"(b1));
}

__device__ __forceinline__ unsigned pack_hi(float x, float y) {
    __half2 h = __halves2half2(__float2half_rn(x), __float2half_rn(y));
    return *reinterpret_cast<unsigned*>(&h);
}
__device__ __forceinline__ unsigned pack_lo(float x, float y) {
    __half hx = __float2half_rn(x), hy = __float2half_rn(y);
    __half2 h = __halves2half2(__float2half_rn(x - __half2float(hx)),
                               __float2half_rn(y - __half2float(hy)));
    return *reinterpret_cast<unsigned*>(&h);
}

__device__ void build_job_tc(
    int job, char* smraw,
    const float* __restrict__ emb,
    const float* __restrict__ w3, const float* __restrict__ w4,
    const float* __restrict__ w5, int tid)
{
    const int tbl = job >> 3;
    const int c0  = ((job >> 2) & 1) * 128;
    const int o0  = (job & 3) * 64;

    int k, j; const float* w;
    if (tbl < 3)      { k = 3; j = tbl;     w = w3; }
    else if (tbl < 7) { k = 4; j = tbl - 3; w = w4; }
    else              { k = 5; j = tbl - 7; w = w5; }
    const int wk = 256 * k;

    __half* Ahi = reinterpret_cast<__half*>(smraw);
    __half* Alo = Ahi + 128 * BSTRIDE;
    __half* Bhi = Alo + 128 * BSTRIDE;
    __half* Blo = Bhi + 64 * BSTRIDE;

    const int warp    = tid >> 5;
    const int lane    = tid & 31;
    const int grp     = lane >> 2;
    const int tig     = lane & 3;
    const int rowblk  = warp & 7;
    const int on_pair = warp >> 3;       // 0..3 -> n8-tiles {2p, 2p+1}
    const int r0      = rowblk * 16 + grp;

    float d[2][4];
    #pragma unroll
    for (int oi = 0; oi < 2; oi++)
        #pragma unroll
        for (int u = 0; u < 4; u++) d[oi][u] = 0.0f;

    for (int chunk = 0; chunk < 4; chunk++) {
        const int i0 = chunk * 64;
        __syncthreads();                        // mma done with smem
        #pragma unroll
        for (int r = 0; r < 4; r++) {           // A: 128c x 64i (32 pairs/row)
            int idx = tid + r * 1024;
            int c   = idx >> 5;
            int p   = idx & 31;
            float2 e = *reinterpret_cast<const float2*>(
                emb + (c0 + c) * 256 + i0 + 2 * p);
            *reinterpret_cast<unsigned*>(&Ahi[c * BSTRIDE + 2 * p]) = pack_hi(e.x, e.y);
            *reinterpret_cast<unsigned*>(&Alo[c * BSTRIDE + 2 * p]) = pack_lo(e.x, e.y);
        }
        #pragma unroll
        for (int r = 0; r < 2; r++) {           // B: 64o x 64i
            int idx = tid + r * 1024;
            int o   = idx >> 5;
            int p   = idx & 31;
            const float* wp = w + (o0 + o) * wk + (i0 + 2 * p) * k + j;
            float vx = wp[0], vy = wp[k];
            *reinterpret_cast<unsigned*>(&Bhi[o * BSTRIDE + 2 * p]) = pack_hi(vx, vy);
            *reinterpret_cast<unsigned*>(&Blo[o * BSTRIDE + 2 * p]) = pack_lo(vx, vy);
        }
        __syncthreads();                        // smem ready

        #pragma unroll
        for (int kc = 0; kc < 64; kc += 16) {
            unsigned ah0 = *reinterpret_cast<unsigned*>(&Ahi[ r0      * BSTRIDE + kc     + 2 * tig]);
            unsigned ah1 = *reinterpret_cast<unsigned*>(&Ahi[(r0 + 8) * BSTRIDE + kc     + 2 * tig]);
            unsigned ah2 = *reinterpret_cast<unsigned*>(&Ahi[ r0      * BSTRIDE + kc + 8 + 2 * tig]);
            unsigned ah3 = *reinterpret_cast<unsigned*>(&Ahi[(r0 + 8) * BSTRIDE + kc + 8 + 2 * tig]);
            unsigned al0 = *reinterpret_cast<unsigned*>(&Alo[ r0      * BSTRIDE + kc     + 2 * tig]);
            unsigned al1 = *reinterpret_cast<unsigned*>(&Alo[(r0 + 8) * BSTRIDE + kc     + 2 * tig]);
            unsigned al2 = *reinterpret_cast<unsigned*>(&Alo[ r0      * BSTRIDE + kc + 8 + 2 * tig]);
            unsigned al3 = *reinterpret_cast<unsigned*>(&Alo[(r0 + 8) * BSTRIDE + kc + 8 + 2 * tig]);
            #pragma unroll
            for (int oi = 0; oi < 2; oi++) {
                int on = on_pair * 2 + oi;
                int ob = (on * 8 + grp) * BSTRIDE;
                unsigned bh0 = *reinterpret_cast<unsigned*>(&Bhi[ob + kc     + 2 * tig]);
                unsigned bh1 = *reinterpret_cast<unsigned*>(&Bhi[ob + kc + 8 + 2 * tig]);
                unsigned bl0 = *reinterpret_cast<unsigned*>(&Blo[ob + kc     + 2 * tig]);
                unsigned bl1 = *reinterpret_cast<unsigned*>(&Blo[ob + kc + 8 + 2 * tig]);
                mma_16816(d[oi], ah0, ah1, ah2, ah3, bh0, bh1);
                mma_16816(d[oi], ah0, ah1, ah2, ah3, bl0, bl1);
                mma_16816(d[oi], al0, al1, al2, al3, bh0, bh1);
            }
        }
    }

    #pragma unroll
    for (int oi = 0; oi < 2; oi++) {
        int on  = on_pair * 2 + oi;
        int col = o0 + on * 8 + 2 * tig;
        __half2 h01 = __floats2half2_rn(d[oi][0], d[oi][1]);
        __half2 h23 = __floats2half2_rn(d[oi][2], d[oi][3]);
        *reinterpret_cast<unsigned*>(
            &g_tbl_h[tbl * 65536 + (c0 + r0) * 256 + col]) =
            *reinterpret_cast<unsigned*>(&h01);
        *reinterpret_cast<unsigned*>(
            &g_tbl_h[tbl * 65536 + (c0 + r0 + 8) * 256 + col]) =
            *reinterpret_cast<unsigned*>(&h23);
    }
}

// ---------------------------------------------------------------------------
// Pool compute phase: addresses extracted inline from packed pk words
// (no a[20] array -> ~20 fewer live registers). Serial-chain adds (R14
// order, bit-identical accumulation).
// ---------------------------------------------------------------------------
#define ADR(pk, p) ((((p) & 1) ? ((pk)[(p) >> 1] >> 16) \
                               : ((pk)[(p) >> 1] & 0xFFFFu)) + lane_off)

template<int K, int S0, int S1, int S2, int S3, int S4>
__device__ __forceinline__ void compute_phase(
    char* sm, const unsigned short* schars,
    const float* __restrict__ bias,
    __half2 acc[2][4],
    int otile, int n_count, int qtotal,
    int warp, int n_sub, unsigned lane_off)
{
    constexpr unsigned SB[5] = {S0 * TBL_BYTES, S1 * TBL_BYTES, S2 * TBL_BYTES,
                                S3 * TBL_BYTES, S4 * TBL_BYTES};

    const float* bp = bias + otile * 64 + (lane_off >> 1);
    __half2 bh[4];
    #pragma unroll
    for (int c = 0; c < 4; c++)
        bh[c] = __floats2half2_rn(bp[2 * c], bp[2 * c + 1]);

    const __half2 NEGINF = __float2half2_rn(-60000.0f);

    #pragma unroll
    for (int it = 0; it < 2; it++) {
        const int q = warp + it * 32;
        if (q < qtotal) {
            const int nl  = q * 4 + n_sub;
            const int nlc = (nl < n_count) ? nl : (n_count - 1);

            const unsigned short* cp = schars + nlc * CHSTRIDE;
            uint4 p0 = *reinterpret_cast<const uint4*>(cp);
            uint4 p1 = *reinterpret_cast<const uint4*>(cp + 8);
            uint2 p2 = *reinterpret_cast<const uint2*>(cp + 16);
            unsigned pk[10] = {p0.x, p0.y, p0.z, p0.w,
                               p1.x, p1.y, p1.z, p1.w, p2.x, p2.y};

            __half2 m0 = NEGINF, m1 = NEGINF, m2 = NEGINF, m3 = NEGINF;
            #pragma unroll
            for (int t = 0; t <= LSEQ - K; t++) {
                uint4 su = *reinterpret_cast<const uint4*>(
                    sm + SB[0] + ADR(pk, t));
                __half2 s0 = *reinterpret_cast<__half2*>(&su.x);
                __half2 s1 = *reinterpret_cast<__half2*>(&su.y);
                __half2 s2 = *reinterpret_cast<__half2*>(&su.z);
                __half2 s3 = *reinterpret_cast<__half2*>(&su.w);
                #pragma unroll
                for (int j = 1; j < K; j++) {
                    uint4 ru = *reinterpret_cast<const uint4*>(
                        sm + SB[j] + ADR(pk, t + j));
                    s0 = __hadd2(s0, *reinterpret_cast<__half2*>(&ru.x));
                    s1 = __hadd2(s1, *reinterpret_cast<__half2*>(&ru.y));
                    s2 = __hadd2(s2, *reinterpret_cast<__half2*>(&ru.z));
                    s3 = __hadd2(s3, *reinterpret_cast<__half2*>(&ru.w));
                }
                m0 = __hmax2(m0, s0);
                m1 = __hmax2(m1, s1);
                m2 = __hmax2(m2, s2);
                m3 = __hmax2(m3, s3);
            }

            acc[it][0] = __hmax2(acc[it][0], __hadd2(m0, bh[0]));
            acc[it][1] = __hmax2(acc[it][1], __hadd2(m1, bh[1]));
            acc[it][2] = __hmax2(acc[it][2], __hadd2(m2, bh[2]));
            acc[it][3] = __hmax2(acc[it][3], __hadd2(m3, bh[3]));
        }
    }
}

// ---------------------------------------------------------------------------
__global__ void __launch_bounds__(1024, 1)
fused_cnn_kernel(const int* __restrict__ x, const int* __restrict__ lens,
                 const float* __restrict__ emb,
                 const float* __restrict__ w3, const float* __restrict__ b3,
                 const float* __restrict__ w4, const float* __restrict__ b4,
                 const float* __restrict__ w5, const float* __restrict__ b5,
                 float* __restrict__ out)
{
    extern __shared__ char sm[];
    const int tid     = threadIdx.x;
    const int group   = blockIdx.x;
    const int otile   = blockIdx.y;
    const int bid     = otile * NGRP + group;     // 0..147
    const int n_start = group * NPC;
    const int n_count = min(NTOT - n_start, NPC);

    unsigned short* schars = reinterpret_cast<unsigned short*>(sm + SMEM_CHARS_OFF);
    const bool builder = (bid < 96);              // CTA-uniform

    // ---- prologue: builder CTAs run the build with ALL 1024 threads
    //      (chars staged later, overlapped with boundary-1 cp.async wait);
    //      non-builder CTAs stage chars with all 1024 threads.
    if (builder) {
        build_job_tc(bid, sm, emb, w3, w4, w5, tid);
    } else {
        for (int i = tid; i < n_count * LSEQ; i += 1024) {
            int n = i / LSEQ, p = i - n * LSEQ;
            schars[n * CHSTRIDE + p] =
                (unsigned short)(x[(n_start + n) * LSEQ + p] << 7);
        }
    }

    // ---- grid barrier (sense-reversing via generation counter; replay-safe)
    __threadfence();
    __syncthreads();
    if (tid == 0) {
        unsigned gen = g_gen;
        __threadfence();
        if (atomicAdd(&g_count, 1) == NCTA - 1) {
            atomicExch(&g_count, 0);
            __threadfence();
            g_gen = gen + 1;
        } else {
            while (g_gen == gen) { }
        }
    }
    __syncthreads();

    // ---- pool: 5-slot, ALL staging exposed at boundaries (R14 proven).
    //      phase3 {0,1,2}; phase4 {3,4,0,1}; phase5 {2,3,4,0,1}.
    const unsigned sm_u32 = (unsigned)__cvta_generic_to_shared(sm);
    const __half* T = g_tbl_h + otile * 64;

    const int lane  = tid & 31;
    const int warp  = tid >> 5;
    const int n_sub = lane >> 3;
    const unsigned lane_off = (unsigned)((lane & 7) * 16);
    const int qtotal = (n_count + 3) >> 2;

    __half2 acc[2][4];
    #pragma unroll
    for (int i = 0; i < 2; i++)
        #pragma unroll
        for (int c = 0; c < 4; c++) acc[i][c] = __float2half2_rn(0.0f);

    // boundary 1: stage k3 (slots 0-2); builder CTAs stage chars under the
    // cp.async wait (LDG latency overlaps the 96KB slot transfer).
    stage_slice(sm_u32, 0, T + 0 * 65536, tid);
    stage_slice(sm_u32, 1, T + 1 * 65536, tid);
    stage_slice(sm_u32, 2, T + 2 * 65536, tid);
    CP_COMMIT();
    if (builder) {
        for (int i = tid; i < n_count * LSEQ; i += 1024) {
            int n = i / LSEQ, p = i - n * LSEQ;
            schars[n * CHSTRIDE + p] =
                (unsigned short)(x[(n_start + n) * LSEQ + p] << 7);
        }
    }
    CP_WAIT0(); __syncthreads();

    compute_phase<3, 0, 1, 2, 0, 0>(sm, schars, b3, acc, otile, n_count,
                                    qtotal, warp, n_sub, lane_off);

    // boundary 2: stage k4 j0-3 -> slots 3,4,0,1 (k3 done)
    __syncthreads();
    stage_slice(sm_u32, 3, T + 3 * 65536, tid);
    stage_slice(sm_u32, 4, T + 4 * 65536, tid);
    stage_slice(sm_u32, 0, T + 5 * 65536, tid);
    stage_slice(sm_u32, 1, T + 6 * 65536, tid);
    CP_COMMIT(); CP_WAIT0(); __syncthreads();

    compute_phase<4, 3, 4, 0, 1, 0>(sm, schars, b4, acc, otile, n_count,
                                    qtotal, warp, n_sub, lane_off);

    // boundary 3: stage k5 j0-4 -> slots 2,3,4,0,1 (k4 done)
    __syncthreads();
    stage_slice(sm_u32, 2, T +  7 * 65536, tid);
    stage_slice(sm_u32, 3, T +  8 * 65536, tid);
    stage_slice(sm_u32, 4, T +  9 * 65536, tid);
    stage_slice(sm_u32, 0, T + 10 * 65536, tid);
    stage_slice(sm_u32, 1, T + 11 * 65536, tid);
    CP_COMMIT(); CP_WAIT0(); __syncthreads();

    compute_phase<5, 2, 3, 4, 0, 1>(sm, schars, b5, acc, otile, n_count,
                                    qtotal, warp, n_sub, lane_off);

    // ---- epilogue: one pure store per (n, 8-output slice); masked -> zeros.
    #pragma unroll
    for (int it = 0; it < 2; it++) {
        const int q  = warp + it * 32;
        const int nl = q * 4 + n_sub;
        if (q < qtotal && nl < n_count) {
            const int n = n_start + nl;
            float4 o0 = make_float4(0.f, 0.f, 0.f, 0.f);
            float4 o1 = o0;
            if (lens[n] != 0) {
                float2 f0 = __half22float2(acc[it][0]);
                float2 f1 = __half22float2(acc[it][1]);
                float2 f2 = __half22float2(acc[it][2]);
                float2 f3 = __half22float2(acc[it][3]);
                o0 = make_float4(f0.x, f0.y, f1.x, f1.y);
                o1 = make_float4(f2.x, f2.y, f3.x, f3.y);
            }
            float4* po = reinterpret_cast<float4*>(
                &out[(size_t)n * 256 + otile * 64 + (lane_off >> 1)]);
            po[0] = o0;
            po[1] = o1;
        }
    }
}

// ---------------------------------------------------------------------------
extern "C" void kernel_launch(void* const* d_in, const int* in_sizes, int n_in,
                              void* d_out, int out_size)
{
    const int*   x    = (const int*)  d_in[0];
    const int*   lens = (const int*)  d_in[1];
    const float* emb  = (const float*)d_in[2];
    const float* w3   = (const float*)d_in[3];
    const float* b3   = (const float*)d_in[4];
    const float* w4   = (const float*)d_in[5];
    const float* b4   = (const float*)d_in[6];
    const float* w5   = (const float*)d_in[7];
    const float* b5   = (const float*)d_in[8];
    float* out = (float*)d_out;

    cudaFuncSetAttribute(fused_cnn_kernel,
                         cudaFuncAttributeMaxDynamicSharedMemorySize, SMEM_TOTAL);
    fused_cnn_kernel<<<dim3(NGRP, OTILES), 1024, SMEM_TOTAL>>>(
        x, lens, emb, w3, b3, w4, b4, w5, b5, out);
}